// round 12
// baseline (speedup 1.0000x reference)
#include <cuda_runtime.h>
#include <cuda_bf16.h>

// RocketConv: 84 ternary dilated kernels (alpha=-1, beta=2 at each
// lexicographic 3-combination of 9 taps), dilation 4, pad 16.
// y = -S + 3*(tap_a + tap_b + tap_c), S = sum of all 9 taps.
// Output plane index within batch: idx = c*84 + k (reshape is reinterpretation).
//
// FINAL (verified best): 4 t/thread, one float4 store per kernel plane
// (warp burst = 512B fully contiguous, full sectors), default caching
// stores, 2 CTAs/SM via 76KB smem limiter. Sits at the DRAM
// sustained-write ceiling (~5.45 TB/s): ncu 54.3-54.8us, DRAM 68-69%.
// Falsified levers (one experiment each): occupancy up (R3, worse),
// split 8t/thread stores (R4, partial-sector RMW), finer grid (R5,
// neutral), st.global.cs (R7, -45%), sequential k-outer streams (R9, -160%).

#define T_LEN 4096
#define C_LEN 16
#define NK 84

extern __shared__ float smem_unused[];  // occupancy limiter only

__global__ __launch_bounds__(256) void rocketconv_kernel(
    const float* __restrict__ x, float* __restrict__ out)
{
    // blockIdx.x in [0, 1024): row = b*16+c (0..255), tile = quarter of T
    const int row  = blockIdx.x >> 2;
    const int tile = blockIdx.x & 3;
    const int t0   = tile * 1024 + threadIdx.x * 4;

    const float* __restrict__ xr = x + row * T_LEN;

    // v[i] = x[t0 - 16 + i], i in [0,36): tap j for lane q is v[q + 4*j]
    float v[36];
#pragma unroll
    for (int i = 0; i < 9; i++) {
        const int t = t0 - 16 + i * 4;
        if (t >= 0 && t + 3 < T_LEN) {
            const float4 f = *reinterpret_cast<const float4*>(xr + t);
            v[i * 4 + 0] = f.x; v[i * 4 + 1] = f.y;
            v[i * 4 + 2] = f.z; v[i * 4 + 3] = f.w;
        } else {
#pragma unroll
            for (int q = 0; q < 4; q++) {
                const int tt = t + q;
                v[i * 4 + q] = (tt >= 0 && tt < T_LEN) ? xr[tt] : 0.0f;
            }
        }
    }

    // -S per lane (S = sum of 9 taps)
    float nS[4];
#pragma unroll
    for (int q = 0; q < 4; q++) {
        float s = 0.0f;
#pragma unroll
        for (int j = 0; j < 9; j++) s += v[q + 4 * j];
        nS[q] = -s;
    }

    // out base: plane idx = c*84 inside batch b; row = b*16+c
    const int b = row >> 4;
    const int c = row & 15;
    float* __restrict__ o =
        out + ((size_t)b * NK * C_LEN + (size_t)c * NK) * T_LEN + t0;

    // 84 kernels in lexicographic combination order, fully unrolled so all
    // tap indices are compile-time constants (registers, no local memory).
#pragma unroll
    for (int a = 0; a < 9; a++) {
#pragma unroll
        for (int bb = a + 1; bb < 9; bb++) {
#pragma unroll
            for (int cc = bb + 1; cc < 9; cc++) {
                float4 r;
                r.x = fmaf(3.0f, v[0 + 4*a] + v[0 + 4*bb] + v[0 + 4*cc], nS[0]);
                r.y = fmaf(3.0f, v[1 + 4*a] + v[1 + 4*bb] + v[1 + 4*cc], nS[1]);
                r.z = fmaf(3.0f, v[2 + 4*a] + v[2 + 4*bb] + v[2 + 4*cc], nS[2]);
                r.w = fmaf(3.0f, v[3 + 4*a] + v[3 + 4*bb] + v[3 + 4*cc], nS[3]);
                *reinterpret_cast<float4*>(o) = r;
                o += T_LEN;  // next kernel plane (contiguous within (b,c))
            }
        }
    }
}

extern "C" void kernel_launch(void* const* d_in, const int* in_sizes, int n_in,
                              void* d_out, int out_size)
{
    const float* x = (const float*)d_in[0];
    float* out = (float*)d_out;

    cudaFuncSetAttribute(rocketconv_kernel,
                         cudaFuncAttributeMaxDynamicSharedMemorySize,
                         76 * 1024);

    // 1024 blocks of 256 threads; 76KB smem reservation -> 2 CTAs/SM.
    rocketconv_kernel<<<1024, 256, 76 * 1024>>>(x, out);
}

// round 13
// speedup vs baseline: 1.0056x; 1.0056x over previous
#include <cuda_runtime.h>
#include <cuda_bf16.h>

// RocketConv: 84 ternary dilated kernels (alpha=-1, beta=2 at each
// lexicographic 3-combination of 9 taps), dilation 4, pad 16.
// y = -S + 3*(tap_a + tap_b + tap_c), S = sum of all 9 taps.
// Output plane index within batch: idx = c*84 + k (reshape is reinterpretation).
//
// FINAL (verified best): 4 t/thread, one float4 store per kernel plane
// (warp burst = 512B fully contiguous, full sectors), default caching
// stores, 2 CTAs/SM via 76KB smem limiter. Sits at the DRAM
// sustained-write ceiling (~5.45 TB/s): ncu 54.3-55.2us, DRAM 67-69%
// across four identical-binary runs.
// Falsified levers (one experiment each): occupancy up (R3, worse),
// split 8t/thread stores (R4, partial-sector RMW), finer grid (R5,
// neutral), st.global.cs (R7, -45%), sequential k-outer streams (R9, -160%).

#define T_LEN 4096
#define C_LEN 16
#define NK 84

extern __shared__ float smem_unused[];  // occupancy limiter only

__global__ __launch_bounds__(256) void rocketconv_kernel(
    const float* __restrict__ x, float* __restrict__ out)
{
    // blockIdx.x in [0, 1024): row = b*16+c (0..255), tile = quarter of T
    const int row  = blockIdx.x >> 2;
    const int tile = blockIdx.x & 3;
    const int t0   = tile * 1024 + threadIdx.x * 4;

    const float* __restrict__ xr = x + row * T_LEN;

    // v[i] = x[t0 - 16 + i], i in [0,36): tap j for lane q is v[q + 4*j]
    float v[36];
#pragma unroll
    for (int i = 0; i < 9; i++) {
        const int t = t0 - 16 + i * 4;
        if (t >= 0 && t + 3 < T_LEN) {
            const float4 f = *reinterpret_cast<const float4*>(xr + t);
            v[i * 4 + 0] = f.x; v[i * 4 + 1] = f.y;
            v[i * 4 + 2] = f.z; v[i * 4 + 3] = f.w;
        } else {
#pragma unroll
            for (int q = 0; q < 4; q++) {
                const int tt = t + q;
                v[i * 4 + q] = (tt >= 0 && tt < T_LEN) ? xr[tt] : 0.0f;
            }
        }
    }

    // -S per lane (S = sum of 9 taps)
    float nS[4];
#pragma unroll
    for (int q = 0; q < 4; q++) {
        float s = 0.0f;
#pragma unroll
        for (int j = 0; j < 9; j++) s += v[q + 4 * j];
        nS[q] = -s;
    }

    // out base: plane idx = c*84 inside batch b; row = b*16+c
    const int b = row >> 4;
    const int c = row & 15;
    float* __restrict__ o =
        out + ((size_t)b * NK * C_LEN + (size_t)c * NK) * T_LEN + t0;

    // 84 kernels in lexicographic combination order, fully unrolled so all
    // tap indices are compile-time constants (registers, no local memory).
#pragma unroll
    for (int a = 0; a < 9; a++) {
#pragma unroll
        for (int bb = a + 1; bb < 9; bb++) {
#pragma unroll
            for (int cc = bb + 1; cc < 9; cc++) {
                float4 r;
                r.x = fmaf(3.0f, v[0 + 4*a] + v[0 + 4*bb] + v[0 + 4*cc], nS[0]);
                r.y = fmaf(3.0f, v[1 + 4*a] + v[1 + 4*bb] + v[1 + 4*cc], nS[1]);
                r.z = fmaf(3.0f, v[2 + 4*a] + v[2 + 4*bb] + v[2 + 4*cc], nS[2]);
                r.w = fmaf(3.0f, v[3 + 4*a] + v[3 + 4*bb] + v[3 + 4*cc], nS[3]);
                *reinterpret_cast<float4*>(o) = r;
                o += T_LEN;  // next kernel plane (contiguous within (b,c))
            }
        }
    }
}

extern "C" void kernel_launch(void* const* d_in, const int* in_sizes, int n_in,
                              void* d_out, int out_size)
{
    const float* x = (const float*)d_in[0];
    float* out = (float*)d_out;

    cudaFuncSetAttribute(rocketconv_kernel,
                         cudaFuncAttributeMaxDynamicSharedMemorySize,
                         76 * 1024);

    // 1024 blocks of 256 threads; 76KB smem reservation -> 2 CTAs/SM.
    rocketconv_kernel<<<1024, 256, 76 * 1024>>>(x, out);
}

// round 16
// speedup vs baseline: 1.0118x; 1.0062x over previous
#include <cuda_runtime.h>
#include <cuda_bf16.h>

// RocketConv: 84 ternary dilated kernels (alpha=-1, beta=2 at each
// lexicographic 3-combination of 9 taps), dilation 4, pad 16.
// y = -S + 3*(tap_a + tap_b + tap_c), S = sum of all 9 taps.
// Output plane index within batch: idx = c*84 + k (reshape is reinterpretation).
//
// FINAL (verified best): 4 t/thread, one float4 store per kernel plane
// (warp burst = 512B fully contiguous, full sectors), default caching
// stores, 2 CTAs/SM via 76KB smem limiter. Sits at the DRAM
// sustained-write ceiling (~5.4 TB/s): ncu 54.3-55.6us, DRAM 67-69%
// across five identical-binary runs.
// Falsified levers (one experiment each): occupancy up (R3, worse),
// split 8t/thread stores (R4, partial-sector RMW), finer grid (R5,
// neutral), st.global.cs (R7, -45%), sequential k-outer streams (R9, -160%).

#define T_LEN 4096
#define C_LEN 16
#define NK 84

extern __shared__ float smem_unused[];  // occupancy limiter only

__global__ __launch_bounds__(256) void rocketconv_kernel(
    const float* __restrict__ x, float* __restrict__ out)
{
    // blockIdx.x in [0, 1024): row = b*16+c (0..255), tile = quarter of T
    const int row  = blockIdx.x >> 2;
    const int tile = blockIdx.x & 3;
    const int t0   = tile * 1024 + threadIdx.x * 4;

    const float* __restrict__ xr = x + row * T_LEN;

    // v[i] = x[t0 - 16 + i], i in [0,36): tap j for lane q is v[q + 4*j]
    float v[36];
#pragma unroll
    for (int i = 0; i < 9; i++) {
        const int t = t0 - 16 + i * 4;
        if (t >= 0 && t + 3 < T_LEN) {
            const float4 f = *reinterpret_cast<const float4*>(xr + t);
            v[i * 4 + 0] = f.x; v[i * 4 + 1] = f.y;
            v[i * 4 + 2] = f.z; v[i * 4 + 3] = f.w;
        } else {
#pragma unroll
            for (int q = 0; q < 4; q++) {
                const int tt = t + q;
                v[i * 4 + q] = (tt >= 0 && tt < T_LEN) ? xr[tt] : 0.0f;
            }
        }
    }

    // -S per lane (S = sum of 9 taps)
    float nS[4];
#pragma unroll
    for (int q = 0; q < 4; q++) {
        float s = 0.0f;
#pragma unroll
        for (int j = 0; j < 9; j++) s += v[q + 4 * j];
        nS[q] = -s;
    }

    // out base: plane idx = c*84 inside batch b; row = b*16+c
    const int b = row >> 4;
    const int c = row & 15;
    float* __restrict__ o =
        out + ((size_t)b * NK * C_LEN + (size_t)c * NK) * T_LEN + t0;

    // 84 kernels in lexicographic combination order, fully unrolled so all
    // tap indices are compile-time constants (registers, no local memory).
#pragma unroll
    for (int a = 0; a < 9; a++) {
#pragma unroll
        for (int bb = a + 1; bb < 9; bb++) {
#pragma unroll
            for (int cc = bb + 1; cc < 9; cc++) {
                float4 r;
                r.x = fmaf(3.0f, v[0 + 4*a] + v[0 + 4*bb] + v[0 + 4*cc], nS[0]);
                r.y = fmaf(3.0f, v[1 + 4*a] + v[1 + 4*bb] + v[1 + 4*cc], nS[1]);
                r.z = fmaf(3.0f, v[2 + 4*a] + v[2 + 4*bb] + v[2 + 4*cc], nS[2]);
                r.w = fmaf(3.0f, v[3 + 4*a] + v[3 + 4*bb] + v[3 + 4*cc], nS[3]);
                *reinterpret_cast<float4*>(o) = r;
                o += T_LEN;  // next kernel plane (contiguous within (b,c))
            }
        }
    }
}

extern "C" void kernel_launch(void* const* d_in, const int* in_sizes, int n_in,
                              void* d_out, int out_size)
{
    const float* x = (const float*)d_in[0];
    float* out = (float*)d_out;

    cudaFuncSetAttribute(rocketconv_kernel,
                         cudaFuncAttributeMaxDynamicSharedMemorySize,
                         76 * 1024);

    // 1024 blocks of 256 threads; 76KB smem reservation -> 2 CTAs/SM.
    rocketconv_kernel<<<1024, 256, 76 * 1024>>>(x, out);
}

// round 17
// speedup vs baseline: 1.0180x; 1.0062x over previous
#include <cuda_runtime.h>
#include <cuda_bf16.h>

// RocketConv: 84 ternary dilated kernels (alpha=-1, beta=2 at each
// lexicographic 3-combination of 9 taps), dilation 4, pad 16.
// y = -S + 3*(tap_a + tap_b + tap_c), S = sum of all 9 taps.
// Output plane index within batch: idx = c*84 + k (reshape is reinterpretation).
//
// FINAL (verified best): 4 t/thread, one float4 store per kernel plane
// (warp burst = 512B fully contiguous, full sectors), default caching
// stores, 2 CTAs/SM via 76KB smem limiter. Sits at the DRAM
// sustained-write ceiling (~5.4 TB/s): ncu 54.3-55.6us, DRAM 67-69%
// across six identical-binary runs.
// Falsified levers (one experiment each): occupancy up (R3, worse),
// split 8t/thread stores (R4, partial-sector RMW), finer grid (R5,
// neutral), st.global.cs (R7, -45%), sequential k-outer streams (R9, -160%).
// Rejected by rule: L2-persistence window (needs device-limit change).

#define T_LEN 4096
#define C_LEN 16
#define NK 84

extern __shared__ float smem_unused[];  // occupancy limiter only

__global__ __launch_bounds__(256) void rocketconv_kernel(
    const float* __restrict__ x, float* __restrict__ out)
{
    // blockIdx.x in [0, 1024): row = b*16+c (0..255), tile = quarter of T
    const int row  = blockIdx.x >> 2;
    const int tile = blockIdx.x & 3;
    const int t0   = tile * 1024 + threadIdx.x * 4;

    const float* __restrict__ xr = x + row * T_LEN;

    // v[i] = x[t0 - 16 + i], i in [0,36): tap j for lane q is v[q + 4*j]
    float v[36];
#pragma unroll
    for (int i = 0; i < 9; i++) {
        const int t = t0 - 16 + i * 4;
        if (t >= 0 && t + 3 < T_LEN) {
            const float4 f = *reinterpret_cast<const float4*>(xr + t);
            v[i * 4 + 0] = f.x; v[i * 4 + 1] = f.y;
            v[i * 4 + 2] = f.z; v[i * 4 + 3] = f.w;
        } else {
#pragma unroll
            for (int q = 0; q < 4; q++) {
                const int tt = t + q;
                v[i * 4 + q] = (tt >= 0 && tt < T_LEN) ? xr[tt] : 0.0f;
            }
        }
    }

    // -S per lane (S = sum of 9 taps)
    float nS[4];
#pragma unroll
    for (int q = 0; q < 4; q++) {
        float s = 0.0f;
#pragma unroll
        for (int j = 0; j < 9; j++) s += v[q + 4 * j];
        nS[q] = -s;
    }

    // out base: plane idx = c*84 inside batch b; row = b*16+c
    const int b = row >> 4;
    const int c = row & 15;
    float* __restrict__ o =
        out + ((size_t)b * NK * C_LEN + (size_t)c * NK) * T_LEN + t0;

    // 84 kernels in lexicographic combination order, fully unrolled so all
    // tap indices are compile-time constants (registers, no local memory).
#pragma unroll
    for (int a = 0; a < 9; a++) {
#pragma unroll
        for (int bb = a + 1; bb < 9; bb++) {
#pragma unroll
            for (int cc = bb + 1; cc < 9; cc++) {
                float4 r;
                r.x = fmaf(3.0f, v[0 + 4*a] + v[0 + 4*bb] + v[0 + 4*cc], nS[0]);
                r.y = fmaf(3.0f, v[1 + 4*a] + v[1 + 4*bb] + v[1 + 4*cc], nS[1]);
                r.z = fmaf(3.0f, v[2 + 4*a] + v[2 + 4*bb] + v[2 + 4*cc], nS[2]);
                r.w = fmaf(3.0f, v[3 + 4*a] + v[3 + 4*bb] + v[3 + 4*cc], nS[3]);
                *reinterpret_cast<float4*>(o) = r;
                o += T_LEN;  // next kernel plane (contiguous within (b,c))
            }
        }
    }
}

extern "C" void kernel_launch(void* const* d_in, const int* in_sizes, int n_in,
                              void* d_out, int out_size)
{
    const float* x = (const float*)d_in[0];
    float* out = (float*)d_out;

    cudaFuncSetAttribute(rocketconv_kernel,
                         cudaFuncAttributeMaxDynamicSharedMemorySize,
                         76 * 1024);

    // 1024 blocks of 256 threads; 76KB smem reservation -> 2 CTAs/SM.
    rocketconv_kernel<<<1024, 256, 76 * 1024>>>(x, out);
}